// round 10
// baseline (speedup 1.0000x reference)
#include <cuda_runtime.h>
#include <cuda_bf16.h>
#include <cstdint>

// Grid_nd_sample: bilinear interpolation gather — persistent cp.async pipeline.
// in_tensor: (B=16, H=128, W=128, C=256) fp32
// indices:   (B=16, P=8192, 2) fp32  -- coord0 = H axis, coord1 = W axis
// out:       (B, P, C) fp32
//
// 888 persistent blocks (148 SM x 6), grid-stride over 4096 groups of 32
// points. The 2-stage cp.async pipeline never drains across groups; next
// group's indices are prefetched ~8 iterations ahead into a double-buffered
// smem slot. mu/pidx are carried in registers from issue-time so the compute
// stage never touches sidx (no group-boundary read race). One __syncthreads
// per 32 points.

static constexpr int B = 16;
static constexpr int H = 128;
static constexpr int W = 128;
static constexpr int C = 256;
static constexpr int P = 8192;
static constexpr int CHUNKS = C / 4;              // 64 float4 per pixel row
static constexpr int GPTS  = 32;                  // points per group
static constexpr int NGROUPS = B * P / GPTS;      // 4096
static constexpr int GRID = 888;                  // 148 SMs * 6 blocks

__device__ __forceinline__ void cp16(uint32_t dst_smem, const void* src_gmem) {
    asm volatile("cp.async.cg.shared.global [%0], [%1], 16;"
                 :: "r"(dst_smem), "l"(src_gmem));
}
#define CP_COMMIT() asm volatile("cp.async.commit_group;" ::: "memory")
#define CP_WAIT1()  asm volatile("cp.async.wait_group 1;" ::: "memory")
#define CP_WAIT0()  asm volatile("cp.async.wait_group 0;" ::: "memory")

__global__ __launch_bounds__(256, 6)
void grid_nd_sample_kernel(const float* __restrict__ in_tensor,
                           const float2* __restrict__ indices,
                           float4* __restrict__ out)
{
    // [stage parity][point-slot][row][chunk] : 2*4*4*64*16B = 32KB
    __shared__ float4 buf[2][4][4][CHUNKS];
    __shared__ float2 sidx[2][GPTS];              // double-buffered group indices

    const unsigned tid   = threadIdx.x;
    const unsigned wid   = tid >> 5;
    const unsigned lane  = tid & 31;
    const unsigned pt4   = wid >> 1;              // point slot 0..3 per stage
    const unsigned hf    = wid & 1;               // half of C this warp owns
    const unsigned chunk = hf * 32 + lane;        // float4 chunk 0..63
    const int bid = blockIdx.x;

    // Groups for this block: g_k = bid + k*GRID, k = 0..ng-1.
    const int ng = (NGROUPS - bid + GRID - 1) / GRID;   // 4 or 5
    const int T  = ng * 8;                               // iterations (even)

    // Stage group 0's indices (one coalesced 256B load).
    if (tid < GPTS)
        sidx[0][tid] = __ldg(&indices[(unsigned)bid * GPTS + tid]);
    __syncthreads();

    const float4* base = (const float4*)in_tensor;

    // issue(t): start gathers for iteration t into buf[t&1]; stash mu/pidx in
    // caller-provided registers. At each group start (t%8==0) warp 0 also
    // prefetches the NEXT group's indices (lands >=6 wait_groups later).
    auto issue = [&](int t, float& smuh, float& smuw, unsigned& sop) {
        int k  = t >> 3;
        int lp = (t & 7) * 4 + (int)pt4;
        unsigned pidx = (unsigned)(bid + k * GRID) * GPTS + lp;
        unsigned b    = pidx >> 13;               // P = 8192 = 2^13
        float2 ind = sidx[k & 1][lp];
        float fh = floorf(ind.x);
        float fw = floorf(ind.y);
        int h0 = (int)fh;
        int w0 = (int)fw;
        int h1 = (int)ceilf(ind.x);
        int w1 = (int)ceilf(ind.y);
        unsigned boff = b * (H * W * CHUNKS);
        const float4* s0 = &base[boff + (h0 * W + w0) * CHUNKS + chunk];
        const float4* s1 = &base[boff + (h1 * W + w0) * CHUNKS + chunk];
        const float4* s2 = &base[boff + (h0 * W + w1) * CHUNKS + chunk];
        const float4* s3 = &base[boff + (h1 * W + w1) * CHUNKS + chunk];
        uint32_t d = (uint32_t)__cvta_generic_to_shared(&buf[t & 1][pt4][0][chunk]);
        const uint32_t ROWB = CHUNKS * 16;        // 1KB per row
        cp16(d + 0 * ROWB, s0);
        cp16(d + 1 * ROWB, s1);
        cp16(d + 2 * ROWB, s2);
        cp16(d + 3 * ROWB, s3);

        if ((t & 7) == 0 && wid == 0) {           // prefetch next group's indices
            int k2 = k + 1;
            if (k2 < ng && lane < 16) {
                uint32_t ds = (uint32_t)__cvta_generic_to_shared(&sidx[k2 & 1][lane * 2]);
                cp16(ds, &indices[(unsigned)(bid + k2 * GRID) * GPTS + lane * 2]);
            }
        }
        smuh = ind.x - fh;
        smuw = ind.y - fw;
        sop  = pidx;
    };

    auto body = [&](int t, float& smuh, float& smuw, unsigned& sop) {
        if (t + 1 < T) { CP_WAIT1(); } else { CP_WAIT0(); }
        // Barrier before issue(t+2) crosses into the next group: publishes the
        // prefetched sidx slot and fences re-use of the old one.
        if ((t & 7) == 6) __syncthreads();

        float4 p1 = buf[t & 1][pt4][0][chunk];
        float4 p2 = buf[t & 1][pt4][1][chunk];
        float4 p3 = buf[t & 1][pt4][2][chunk];
        float4 p4 = buf[t & 1][pt4][3][chunk];

        float mh = smuh, mw = smuw;
        float4 o;
        {
            float a = fmaf(mh, p2.x - p1.x, p1.x);
            float c = fmaf(mh, p4.x - p3.x, p3.x);
            o.x = fmaf(mw, c - a, a);
        }
        {
            float a = fmaf(mh, p2.y - p1.y, p1.y);
            float c = fmaf(mh, p4.y - p3.y, p3.y);
            o.y = fmaf(mw, c - a, a);
        }
        {
            float a = fmaf(mh, p2.z - p1.z, p1.z);
            float c = fmaf(mh, p4.z - p3.z, p3.z);
            o.z = fmaf(mw, c - a, a);
        }
        {
            float a = fmaf(mh, p2.w - p1.w, p1.w);
            float c = fmaf(mh, p4.w - p3.w, p3.w);
            o.w = fmaf(mw, c - a, a);
        }

        __stcs(&out[sop * (unsigned)CHUNKS + chunk], o);

        if (t + 2 < T) { issue(t + 2, smuh, smuw, sop); CP_COMMIT(); }
    };

    // Register-carried pipeline state (two parity slots, no dynamic indexing).
    float mh0, mw0, mh1, mw1;
    unsigned op0, op1;

    issue(0, mh0, mw0, op0); CP_COMMIT();
    issue(1, mh1, mw1, op1); CP_COMMIT();

    for (int t = 0; t < T; t += 2) {
        body(t,     mh0, mw0, op0);
        body(t + 1, mh1, mw1, op1);
    }
}

extern "C" void kernel_launch(void* const* d_in, const int* in_sizes, int n_in,
                              void* d_out, int out_size)
{
    const float*  in_tensor = (const float*)d_in[0];
    const float2* indices   = (const float2*)d_in[1];
    float4*       out       = (float4*)d_out;

    grid_nd_sample_kernel<<<GRID, 256>>>(in_tensor, indices, out);
}